// round 1
// baseline (speedup 1.0000x reference)
#include <cuda_runtime.h>
#include <math.h>

// InteractingLayer (AutoInt): B=4096 batches, F=50 fields, E=64 emb, H=4 heads, D=32.
// out[b,f,h*32+d] = relu( attn_h(Q,K,V)[f,d] + (X @ Wres)[f, h*32+d] )
// Flat view: Q|K|V|R = X[50,64] @ W[64,128]; head h = columns [32h, 32h+32).

#define BB 4096
#define FF 50
#define EE 64
#define HH 4
#define CC 128            // H*D
#define SP 528            // Ps row stride in floats (4 blocks x 132)
#define PS_SZ (FF*SP)     // 26400 floats
#define XT_STRIDE 56
#define KT_STRIDE 52
#define S_STRIDE  52
#define BUFA_SZ 10400     // max( Xt 64*56=3584 , S 4*50*52=10400 )
#define BUFB_SZ 8192      // max( Wst 64*128=8192 , Kt 128*52=6656 )
#define SMEM_FLOATS (PS_SZ + BUFA_SZ + BUFB_SZ)   // 44992
#define SMEM_BYTES  (SMEM_FLOATS * 4)             // 179968

typedef unsigned long long ull;

__device__ __forceinline__ ull pack2(float lo, float hi) {
    ull r; asm("mov.b64 %0,{%1,%2};" : "=l"(r) : "f"(lo), "f"(hi)); return r;
}
__device__ __forceinline__ void unpack2(ull v, float& lo, float& hi) {
    asm("mov.b64 {%0,%1},%2;" : "=f"(lo), "=f"(hi) : "l"(v));
}
// Packed dual-FMA: d.lo += a.lo*b.lo ; d.hi += a.hi*b.hi  (Blackwell f32x2 pipe)
__device__ __forceinline__ void ffma2(ull& d, ull a, ull b) {
    asm("fma.rn.f32x2 %0,%1,%2,%3;" : "=l"(d) : "l"(a), "l"(b), "l"(d));
}

__global__ void __launch_bounds__(512, 1)
autoint_kernel(const float* __restrict__ X,
               const float* __restrict__ Wq, const float* __restrict__ Wk,
               const float* __restrict__ Wv, const float* __restrict__ Wr,
               float* __restrict__ out)
{
    extern __shared__ float sm[];
    float* Ps   = sm;                    // [50][528]: Q@0, K@132, V@264, R@396
    float* bufA = sm + PS_SZ;            // Xt (proj phase) -> S (attn phase)
    float* bufB = sm + PS_SZ + BUFA_SZ;  // Wst (proj phase) -> Kt (scores)

    const int tid  = threadIdx.x;
    const int b    = blockIdx.x;
    const int lane = tid & 31;
    const int warp = tid >> 5;

    const float* Xb = X + (size_t)b * (FF * EE);

    // ---- Load X transposed: Xt[e][f] (stride 56). Makes proj x-loads broadcast + f-vectorized.
    {
        float* Xt = bufA;
        for (int i = tid; i < FF * EE; i += 512) {
            int f = i >> 6, e = i & 63;
            Xt[e * XT_STRIDE + f] = Xb[i];
        }
    }
    __syncthreads();

    // ---- Projections: Ps[f][m*132 + j] = sum_e X[f][e] * Wm[e][j]
    // Thread tile: 4 rows (f = 4*ty..) x 4 cols (j = 4*tx..), f32x2 packed along j.
    {
        const float* Wm[4] = { Wq, Wk, Wv, Wr };
        const float* Xt = bufA;
        const int tx = tid & 31;   // column group (cols 4tx..4tx+3), warp-contiguous
        const int ty = tid >> 5;   // row group (rows 4ty..4ty+3), warp-uniform

        for (int m = 0; m < 4; ++m) {
            // stage W (64x128 = 32KB) into smem; reused by all 16 warps
            {
                float4* dst = (float4*)bufB;
                const float4* src = (const float4*)Wm[m];
                for (int i = tid; i < (EE * CC) / 4; i += 512) dst[i] = src[i];
            }
            __syncthreads();

            ull acc[4][2];
            #pragma unroll
            for (int r = 0; r < 4; ++r) { acc[r][0] = 0ull; acc[r][1] = 0ull; }

            const float* Wst = bufB;
            #pragma unroll 8
            for (int e = 0; e < EE; ++e) {
                float4 wv = *(const float4*)(Wst + e * CC + 4 * tx);   // conflict-free
                ull w01 = pack2(wv.x, wv.y);
                ull w23 = pack2(wv.z, wv.w);
                float4 xv = *(const float4*)(Xt + e * XT_STRIDE + 4 * ty); // broadcast
                ull x0 = pack2(xv.x, xv.x), x1 = pack2(xv.y, xv.y);
                ull x2 = pack2(xv.z, xv.z), x3 = pack2(xv.w, xv.w);
                ffma2(acc[0][0], x0, w01); ffma2(acc[0][1], x0, w23);
                ffma2(acc[1][0], x1, w01); ffma2(acc[1][1], x1, w23);
                ffma2(acc[2][0], x2, w01); ffma2(acc[2][1], x2, w23);
                ffma2(acc[3][0], x3, w01); ffma2(acc[3][1], x3, w23);
            }
            #pragma unroll
            for (int r = 0; r < 4; ++r) {
                int f = 4 * ty + r;
                if (f < FF) {
                    float4 o;
                    unpack2(acc[r][0], o.x, o.y);
                    unpack2(acc[r][1], o.z, o.w);
                    *(float4*)(Ps + f * SP + m * 132 + 4 * tx) = o;
                }
            }
            __syncthreads();
        }
    }

    // ---- Transpose K into Kt[c][g] so score k-loads are row-contiguous (conflict-free)
    {
        float* Kt = bufB;
        for (int i = tid; i < CC * FF; i += 512) {
            int c = i & 127, g = i >> 7;
            Kt[c * KT_STRIDE + g] = Ps[g * SP + 132 + c];
        }
    }
    __syncthreads();

    // ---- Scores: S[h][f][g] = sum_d Q[f][32h+d] * K[g][32h+d]   (unscaled, per reference)
    // Warp task = (h, 4-row f group); lanes over g, f32x2 packs the two g-halves.
    {
        float* S = bufA;
        const float* Kt = bufB;
        for (int t = warp; t < 52; t += 16) {
            int h = t / 13, f0 = 4 * (t % 13);
            int c0 = h * 32;
            ull acc[4];
            #pragma unroll
            for (int r = 0; r < 4; ++r) acc[r] = 0ull;

            #pragma unroll 4
            for (int d = 0; d < 32; ++d) {
                const float* ktrow = Kt + (c0 + d) * KT_STRIDE + lane;
                ull kk = pack2(ktrow[0], ktrow[32]);
                #pragma unroll
                for (int r = 0; r < 4; ++r) {
                    float q = Ps[(f0 + r) * SP + c0 + d];   // broadcast
                    ffma2(acc[r], pack2(q, q), kk);
                }
            }
            #pragma unroll
            for (int r = 0; r < 4; ++r) {
                int f = f0 + r;
                if (f < FF) {
                    float s0, s1; unpack2(acc[r], s0, s1);
                    float* row = S + (h * FF + f) * S_STRIDE;
                    row[lane] = s0;
                    if (lane < FF - 32) row[32 + lane] = s1;
                }
            }
        }
    }
    __syncthreads();

    // ---- Softmax over g (one warp per row, shfl butterfly reductions)
    {
        float* S = bufA;
        for (int row = warp; row < HH * FF; row += 16) {
            float* r = S + row * S_STRIDE;
            float v0 = r[lane];
            float v1 = (lane < FF - 32) ? r[32 + lane] : -3.4e38f;
            float mx = fmaxf(v0, v1);
            #pragma unroll
            for (int o = 16; o; o >>= 1) mx = fmaxf(mx, __shfl_xor_sync(0xffffffffu, mx, o));
            float e0 = __expf(v0 - mx);
            float e1 = (lane < FF - 32) ? __expf(v1 - mx) : 0.f;
            float s = e0 + e1;
            #pragma unroll
            for (int o = 16; o; o >>= 1) s += __shfl_xor_sync(0xffffffffu, s, o);
            float inv = 1.0f / s;
            r[lane] = e0 * inv;
            if (lane < FF - 32) r[32 + lane] = e1 * inv;
        }
    }
    __syncthreads();

    // ---- AV + residual + ReLU -> gmem (coalesced: lane == output column)
    {
        const float* S = bufA;
        int jj = tid & 127;       // output column; warp-uniform head h = jj>>5
        int fb = tid >> 7;        // 0..3
        int h  = jj >> 5;
        const float* Sh = S + h * FF * S_STRIDE;
        float* outB = out + (size_t)b * (FF * CC);

        #pragma unroll
        for (int i = 0; i < 7; ++i) {
            int fA = fb + 8 * i;
            if (fA >= FF) break;
            int fB = fA + 4;
            float accA = 0.f, accB = 0.f;
            const float* rA = Sh + fA * S_STRIDE;
            const float* rB = Sh + fB * S_STRIDE;   // may be OOB row; predicated below
            #pragma unroll
            for (int g4 = 0; g4 < 48; g4 += 4) {
                float4 aA = *(const float4*)(rA + g4);   // broadcast
                float4 aB = *(const float4*)(rB + g4);   // broadcast
                float v0 = Ps[(g4 + 0) * SP + 264 + jj]; // conflict-free rows of V
                float v1 = Ps[(g4 + 1) * SP + 264 + jj];
                float v2 = Ps[(g4 + 2) * SP + 264 + jj];
                float v3 = Ps[(g4 + 3) * SP + 264 + jj];
                accA = fmaf(aA.x, v0, fmaf(aA.y, v1, fmaf(aA.z, v2, fmaf(aA.w, v3, accA))));
                accB = fmaf(aB.x, v0, fmaf(aB.y, v1, fmaf(aB.z, v2, fmaf(aB.w, v3, accB))));
            }
            {   // tail g = 48, 49
                float v0 = Ps[48 * SP + 264 + jj];
                float v1 = Ps[49 * SP + 264 + jj];
                accA += rA[48] * v0 + rA[49] * v1;
                accB += rB[48] * v0 + rB[49] * v1;
            }
            float oA = accA + Ps[fA * SP + 396 + jj];
            outB[fA * CC + jj] = fmaxf(oA, 0.f);
            if (fB < FF) {
                float oB = accB + Ps[fB * SP + 396 + jj];
                outB[fB * CC + jj] = fmaxf(oB, 0.f);
            }
        }
    }
}

extern "C" void kernel_launch(void* const* d_in, const int* in_sizes, int n_in,
                              void* d_out, int out_size)
{
    const float* X  = (const float*)d_in[0];
    const float* Wq = (const float*)d_in[1];
    const float* Wk = (const float*)d_in[2];
    const float* Wv = (const float*)d_in[3];
    const float* Wr = (const float*)d_in[4];
    float* out = (float*)d_out;

    cudaFuncSetAttribute(autoint_kernel,
                         cudaFuncAttributeMaxDynamicSharedMemorySize, SMEM_BYTES);
    autoint_kernel<<<BB, 512, SMEM_BYTES>>>(X, Wq, Wk, Wv, Wr, out);
}

// round 3
// speedup vs baseline: 1.0002x; 1.0002x over previous
#include <cuda_runtime.h>
#include <math.h>

// InteractingLayer (AutoInt): B=4096 batches, F=50 fields, E=64 emb, H=4 heads, D=32.
// out[b,f,h*32+d] = relu( attn_h(Q,K,V)[f,d] + (X @ Wres)[f, h*32+d] )
// Flat view: Q|K|V|R = X[50,64] @ W[64,128]; head h = columns [32h, 32h+32).

#define BB 4096
#define FF 50
#define EE 64
#define HH 4
#define CC 128            // H*D
#define SP 528            // Ps row stride in floats (4 blocks x 132)
#define PS_SZ (FF*SP)     // 26400 floats
#define XT_STRIDE 56
#define KT_STRIDE 52
#define S_STRIDE  52
#define BUFA_SZ 10400     // max( Xt 64*56=3584 , S 4*50*52=10400 )
#define BUFB_SZ 8192      // max( Wst 64*128=8192 , Kt 128*52=6656 )
#define SMEM_FLOATS (PS_SZ + BUFA_SZ + BUFB_SZ)   // 44992
#define SMEM_BYTES  (SMEM_FLOATS * 4)             // 179968

typedef unsigned long long ull;

__device__ __forceinline__ ull pack2(float lo, float hi) {
    ull r; asm("mov.b64 %0,{%1,%2};" : "=l"(r) : "f"(lo), "f"(hi)); return r;
}
__device__ __forceinline__ void unpack2(ull v, float& lo, float& hi) {
    asm("mov.b64 {%0,%1},%2;" : "=f"(lo), "=f"(hi) : "l"(v));
}
// Packed dual-FMA: d.lo += a.lo*b.lo ; d.hi += a.hi*b.hi  (Blackwell f32x2 pipe)
__device__ __forceinline__ void ffma2(ull& d, ull a, ull b) {
    asm("fma.rn.f32x2 %0,%1,%2,%3;" : "=l"(d) : "l"(a), "l"(b), "l"(d));
}

__global__ void __launch_bounds__(512, 1)
autoint_kernel(const float* __restrict__ X,
               const float* __restrict__ Wq, const float* __restrict__ Wk,
               const float* __restrict__ Wv, const float* __restrict__ Wr,
               float* __restrict__ out)
{
    extern __shared__ float sm[];
    float* Ps   = sm;                    // [50][528]: Q@0, K@132, V@264, R@396
    float* bufA = sm + PS_SZ;            // Xt (proj phase) -> S (attn phase)
    float* bufB = sm + PS_SZ + BUFA_SZ;  // Wst (proj phase) -> Kt (scores)

    const int tid  = threadIdx.x;
    const int b    = blockIdx.x;
    const int lane = tid & 31;
    const int warp = tid >> 5;

    const float* Xb = X + (size_t)b * (FF * EE);

    // ---- Load X transposed: Xt[e][f] (stride 56). Makes proj x-loads broadcast + f-vectorized.
    {
        float* Xt = bufA;
        for (int i = tid; i < FF * EE; i += 512) {
            int f = i >> 6, e = i & 63;
            Xt[e * XT_STRIDE + f] = Xb[i];
        }
    }
    __syncthreads();

    // ---- Projections: Ps[f][m*132 + j] = sum_e X[f][e] * Wm[e][j]
    // Thread tile: 4 rows (f = 4*ty..) x 4 cols (j = 4*tx..), f32x2 packed along j.
    {
        const float* Wm[4] = { Wq, Wk, Wv, Wr };
        const float* Xt = bufA;
        const int tx = tid & 31;   // column group (cols 4tx..4tx+3), warp-contiguous
        const int ty = tid >> 5;   // row group (rows 4ty..4ty+3), warp-uniform

        for (int m = 0; m < 4; ++m) {
            // stage W (64x128 = 32KB) into smem; reused by all 16 warps
            {
                float4* dst = (float4*)bufB;
                const float4* src = (const float4*)Wm[m];
                for (int i = tid; i < (EE * CC) / 4; i += 512) dst[i] = src[i];
            }
            __syncthreads();

            ull acc[4][2];
            #pragma unroll
            for (int r = 0; r < 4; ++r) { acc[r][0] = 0ull; acc[r][1] = 0ull; }

            const float* Wst = bufB;
            #pragma unroll 8
            for (int e = 0; e < EE; ++e) {
                float4 wv = *(const float4*)(Wst + e * CC + 4 * tx);   // conflict-free
                ull w01 = pack2(wv.x, wv.y);
                ull w23 = pack2(wv.z, wv.w);
                float4 xv = *(const float4*)(Xt + e * XT_STRIDE + 4 * ty); // broadcast
                ull x0 = pack2(xv.x, xv.x), x1 = pack2(xv.y, xv.y);
                ull x2 = pack2(xv.z, xv.z), x3 = pack2(xv.w, xv.w);
                ffma2(acc[0][0], x0, w01); ffma2(acc[0][1], x0, w23);
                ffma2(acc[1][0], x1, w01); ffma2(acc[1][1], x1, w23);
                ffma2(acc[2][0], x2, w01); ffma2(acc[2][1], x2, w23);
                ffma2(acc[3][0], x3, w01); ffma2(acc[3][1], x3, w23);
            }
            #pragma unroll
            for (int r = 0; r < 4; ++r) {
                int f = 4 * ty + r;
                if (f < FF) {
                    float4 o;
                    unpack2(acc[r][0], o.x, o.y);
                    unpack2(acc[r][1], o.z, o.w);
                    *(float4*)(Ps + f * SP + m * 132 + 4 * tx) = o;
                }
            }
            __syncthreads();
        }
    }

    // ---- Transpose K into Kt[c][g] so score k-loads are row-contiguous (conflict-free)
    {
        float* Kt = bufB;
        for (int i = tid; i < CC * FF; i += 512) {
            int c = i & 127, g = i >> 7;
            Kt[c * KT_STRIDE + g] = Ps[g * SP + 132 + c];
        }
    }
    __syncthreads();

    // ---- Scores: S[h][f][g] = sum_d Q[f][32h+d] * K[g][32h+d]   (unscaled, per reference)
    // Warp task = (h, 4-row f group); lanes over g, f32x2 packs the two g-halves.
    {
        float* S = bufA;
        const float* Kt = bufB;
        for (int t = warp; t < 52; t += 16) {
            int h = t / 13, f0 = 4 * (t % 13);
            int c0 = h * 32;
            ull acc[4];
            #pragma unroll
            for (int r = 0; r < 4; ++r) acc[r] = 0ull;

            #pragma unroll 4
            for (int d = 0; d < 32; ++d) {
                const float* ktrow = Kt + (c0 + d) * KT_STRIDE + lane;
                ull kk = pack2(ktrow[0], ktrow[32]);
                #pragma unroll
                for (int r = 0; r < 4; ++r) {
                    float q = Ps[(f0 + r) * SP + c0 + d];   // broadcast
                    ffma2(acc[r], pack2(q, q), kk);
                }
            }
            #pragma unroll
            for (int r = 0; r < 4; ++r) {
                int f = f0 + r;
                if (f < FF) {
                    float s0, s1; unpack2(acc[r], s0, s1);
                    float* row = S + (h * FF + f) * S_STRIDE;
                    row[lane] = s0;
                    if (lane < FF - 32) row[32 + lane] = s1;
                }
            }
        }
    }
    __syncthreads();

    // ---- Softmax over g (one warp per row, shfl butterfly reductions)
    {
        float* S = bufA;
        for (int row = warp; row < HH * FF; row += 16) {
            float* r = S + row * S_STRIDE;
            float v0 = r[lane];
            float v1 = (lane < FF - 32) ? r[32 + lane] : -3.4e38f;
            float mx = fmaxf(v0, v1);
            #pragma unroll
            for (int o = 16; o; o >>= 1) mx = fmaxf(mx, __shfl_xor_sync(0xffffffffu, mx, o));
            float e0 = __expf(v0 - mx);
            float e1 = (lane < FF - 32) ? __expf(v1 - mx) : 0.f;
            float s = e0 + e1;
            #pragma unroll
            for (int o = 16; o; o >>= 1) s += __shfl_xor_sync(0xffffffffu, s, o);
            float inv = 1.0f / s;
            r[lane] = e0 * inv;
            if (lane < FF - 32) r[32 + lane] = e1 * inv;
        }
    }
    __syncthreads();

    // ---- AV + residual + ReLU -> gmem (coalesced: lane == output column)
    {
        const float* S = bufA;
        int jj = tid & 127;       // output column; warp-uniform head h = jj>>5
        int fb = tid >> 7;        // 0..3
        int h  = jj >> 5;
        const float* Sh = S + h * FF * S_STRIDE;
        float* outB = out + (size_t)b * (FF * CC);

        #pragma unroll
        for (int i = 0; i < 7; ++i) {
            int fA = fb + 8 * i;
            if (fA >= FF) break;
            int fB = fA + 4;
            float accA = 0.f, accB = 0.f;
            const float* rA = Sh + fA * S_STRIDE;
            const float* rB = Sh + fB * S_STRIDE;   // may be OOB row; predicated below
            #pragma unroll
            for (int g4 = 0; g4 < 48; g4 += 4) {
                float4 aA = *(const float4*)(rA + g4);   // broadcast
                float4 aB = *(const float4*)(rB + g4);   // broadcast
                float v0 = Ps[(g4 + 0) * SP + 264 + jj]; // conflict-free rows of V
                float v1 = Ps[(g4 + 1) * SP + 264 + jj];
                float v2 = Ps[(g4 + 2) * SP + 264 + jj];
                float v3 = Ps[(g4 + 3) * SP + 264 + jj];
                accA = fmaf(aA.x, v0, fmaf(aA.y, v1, fmaf(aA.z, v2, fmaf(aA.w, v3, accA))));
                accB = fmaf(aB.x, v0, fmaf(aB.y, v1, fmaf(aB.z, v2, fmaf(aB.w, v3, accB))));
            }
            {   // tail g = 48, 49
                float v0 = Ps[48 * SP + 264 + jj];
                float v1 = Ps[49 * SP + 264 + jj];
                accA += rA[48] * v0 + rA[49] * v1;
                accB += rB[48] * v0 + rB[49] * v1;
            }
            float oA = accA + Ps[fA * SP + 396 + jj];
            outB[fA * CC + jj] = fmaxf(oA, 0.f);
            if (fB < FF) {
                float oB = accB + Ps[fB * SP + 396 + jj];
                outB[fB * CC + jj] = fmaxf(oB, 0.f);
            }
        }
    }
}

extern "C" void kernel_launch(void* const* d_in, const int* in_sizes, int n_in,
                              void* d_out, int out_size)
{
    const float* X  = (const float*)d_in[0];
    const float* Wq = (const float*)d_in[1];
    const float* Wk = (const float*)d_in[2];
    const float* Wv = (const float*)d_in[3];
    const float* Wr = (const float*)d_in[4];
    float* out = (float*)d_out;

    cudaFuncSetAttribute(autoint_kernel,
                         cudaFuncAttributeMaxDynamicSharedMemorySize, SMEM_BYTES);
    autoint_kernel<<<BB, 512, SMEM_BYTES>>>(X, Wq, Wk, Wv, Wr, out);
}

// round 4
// speedup vs baseline: 1.0023x; 1.0021x over previous
#include <cuda_runtime.h>
#include <math.h>

// InteractingLayer (AutoInt): B=4096 batches, F=50 fields, E=64 emb, H=4 heads, D=32.
// out[b,f,h*32+d] = relu( attn_h(Q,K,V)[f,d] + (X @ Wres)[f, h*32+d] )
// Flat view: Q|K|V|R = X[50,64] @ W[64,128]; head h = columns [32h, 32h+32).

#define BB 4096
#define FF 50
#define EE 64
#define HH 4
#define CC 128            // H*D
#define SP 528            // Ps row stride in floats (4 blocks x 132)
#define PS_SZ (FF*SP)     // 26400 floats
#define XT_STRIDE 56
#define KT_STRIDE 52
#define S_STRIDE  52
#define BUFA_SZ 10400     // max( Xt 64*56=3584 , S 4*50*52=10400 )
#define BUFB_SZ 8192      // max( Wst 64*128=8192 , Kt 128*52=6656 )
#define SMEM_FLOATS (PS_SZ + BUFA_SZ + BUFB_SZ)   // 44992
#define SMEM_BYTES  (SMEM_FLOATS * 4)             // 179968

typedef unsigned long long ull;

__device__ __forceinline__ ull pack2(float lo, float hi) {
    ull r; asm("mov.b64 %0,{%1,%2};" : "=l"(r) : "f"(lo), "f"(hi)); return r;
}
__device__ __forceinline__ void unpack2(ull v, float& lo, float& hi) {
    asm("mov.b64 {%0,%1},%2;" : "=f"(lo), "=f"(hi) : "l"(v));
}
// Packed dual-FMA: d.lo += a.lo*b.lo ; d.hi += a.hi*b.hi  (Blackwell f32x2 pipe)
__device__ __forceinline__ void ffma2(ull& d, ull a, ull b) {
    asm("fma.rn.f32x2 %0,%1,%2,%3;" : "=l"(d) : "l"(a), "l"(b), "l"(d));
}

__global__ void __launch_bounds__(512, 1)
autoint_kernel(const float* __restrict__ X,
               const float* __restrict__ Wq, const float* __restrict__ Wk,
               const float* __restrict__ Wv, const float* __restrict__ Wr,
               float* __restrict__ out)
{
    extern __shared__ float sm[];
    float* Ps   = sm;                    // [50][528]: Q@0, K@132, V@264, R@396
    float* bufA = sm + PS_SZ;            // Xt (proj phase) -> S (attn phase)
    float* bufB = sm + PS_SZ + BUFA_SZ;  // Wst (proj phase) -> Kt (scores)

    const int tid  = threadIdx.x;
    const int b    = blockIdx.x;
    const int lane = tid & 31;
    const int warp = tid >> 5;

    const float* Xb = X + (size_t)b * (FF * EE);

    // ---- Load X transposed: Xt[e][f] (stride 56). Makes proj x-loads broadcast + f-vectorized.
    {
        float* Xt = bufA;
        for (int i = tid; i < FF * EE; i += 512) {
            int f = i >> 6, e = i & 63;
            Xt[e * XT_STRIDE + f] = Xb[i];
        }
    }
    __syncthreads();

    // ---- Projections: Ps[f][m*132 + j] = sum_e X[f][e] * Wm[e][j]
    // Thread tile: 4 rows (f = 4*ty..) x 4 cols (j = 4*tx..), f32x2 packed along j.
    {
        const float* Wm[4] = { Wq, Wk, Wv, Wr };
        const float* Xt = bufA;
        const int tx = tid & 31;   // column group (cols 4tx..4tx+3), warp-contiguous
        const int ty = tid >> 5;   // row group (rows 4ty..4ty+3), warp-uniform

        for (int m = 0; m < 4; ++m) {
            // stage W (64x128 = 32KB) into smem; reused by all 16 warps
            {
                float4* dst = (float4*)bufB;
                const float4* src = (const float4*)Wm[m];
                for (int i = tid; i < (EE * CC) / 4; i += 512) dst[i] = src[i];
            }
            __syncthreads();

            ull acc[4][2];
            #pragma unroll
            for (int r = 0; r < 4; ++r) { acc[r][0] = 0ull; acc[r][1] = 0ull; }

            const float* Wst = bufB;
            #pragma unroll 8
            for (int e = 0; e < EE; ++e) {
                float4 wv = *(const float4*)(Wst + e * CC + 4 * tx);   // conflict-free
                ull w01 = pack2(wv.x, wv.y);
                ull w23 = pack2(wv.z, wv.w);
                float4 xv = *(const float4*)(Xt + e * XT_STRIDE + 4 * ty); // broadcast
                ull x0 = pack2(xv.x, xv.x), x1 = pack2(xv.y, xv.y);
                ull x2 = pack2(xv.z, xv.z), x3 = pack2(xv.w, xv.w);
                ffma2(acc[0][0], x0, w01); ffma2(acc[0][1], x0, w23);
                ffma2(acc[1][0], x1, w01); ffma2(acc[1][1], x1, w23);
                ffma2(acc[2][0], x2, w01); ffma2(acc[2][1], x2, w23);
                ffma2(acc[3][0], x3, w01); ffma2(acc[3][1], x3, w23);
            }
            #pragma unroll
            for (int r = 0; r < 4; ++r) {
                int f = 4 * ty + r;
                if (f < FF) {
                    float4 o;
                    unpack2(acc[r][0], o.x, o.y);
                    unpack2(acc[r][1], o.z, o.w);
                    *(float4*)(Ps + f * SP + m * 132 + 4 * tx) = o;
                }
            }
            __syncthreads();
        }
    }

    // ---- Transpose K into Kt[c][g] so score k-loads are row-contiguous (conflict-free)
    {
        float* Kt = bufB;
        for (int i = tid; i < CC * FF; i += 512) {
            int c = i & 127, g = i >> 7;
            Kt[c * KT_STRIDE + g] = Ps[g * SP + 132 + c];
        }
    }
    __syncthreads();

    // ---- Scores: S[h][f][g] = sum_d Q[f][32h+d] * K[g][32h+d]   (unscaled, per reference)
    // Warp task = (h, 4-row f group); lanes over g, f32x2 packs the two g-halves.
    {
        float* S = bufA;
        const float* Kt = bufB;
        for (int t = warp; t < 52; t += 16) {
            int h = t / 13, f0 = 4 * (t % 13);
            int c0 = h * 32;
            ull acc[4];
            #pragma unroll
            for (int r = 0; r < 4; ++r) acc[r] = 0ull;

            #pragma unroll 4
            for (int d = 0; d < 32; ++d) {
                const float* ktrow = Kt + (c0 + d) * KT_STRIDE + lane;
                ull kk = pack2(ktrow[0], ktrow[32]);
                #pragma unroll
                for (int r = 0; r < 4; ++r) {
                    float q = Ps[(f0 + r) * SP + c0 + d];   // broadcast
                    ffma2(acc[r], pack2(q, q), kk);
                }
            }
            #pragma unroll
            for (int r = 0; r < 4; ++r) {
                int f = f0 + r;
                if (f < FF) {
                    float s0, s1; unpack2(acc[r], s0, s1);
                    float* row = S + (h * FF + f) * S_STRIDE;
                    row[lane] = s0;
                    if (lane < FF - 32) row[32 + lane] = s1;
                }
            }
        }
    }
    __syncthreads();

    // ---- Softmax over g (one warp per row, shfl butterfly reductions)
    {
        float* S = bufA;
        for (int row = warp; row < HH * FF; row += 16) {
            float* r = S + row * S_STRIDE;
            float v0 = r[lane];
            float v1 = (lane < FF - 32) ? r[32 + lane] : -3.4e38f;
            float mx = fmaxf(v0, v1);
            #pragma unroll
            for (int o = 16; o; o >>= 1) mx = fmaxf(mx, __shfl_xor_sync(0xffffffffu, mx, o));
            float e0 = __expf(v0 - mx);
            float e1 = (lane < FF - 32) ? __expf(v1 - mx) : 0.f;
            float s = e0 + e1;
            #pragma unroll
            for (int o = 16; o; o >>= 1) s += __shfl_xor_sync(0xffffffffu, s, o);
            float inv = 1.0f / s;
            r[lane] = e0 * inv;
            if (lane < FF - 32) r[32 + lane] = e1 * inv;
        }
    }
    __syncthreads();

    // ---- AV + residual + ReLU -> gmem (coalesced: lane == output column)
    {
        const float* S = bufA;
        int jj = tid & 127;       // output column; warp-uniform head h = jj>>5
        int fb = tid >> 7;        // 0..3
        int h  = jj >> 5;
        const float* Sh = S + h * FF * S_STRIDE;
        float* outB = out + (size_t)b * (FF * CC);

        #pragma unroll
        for (int i = 0; i < 7; ++i) {
            int fA = fb + 8 * i;
            if (fA >= FF) break;
            int fB = fA + 4;
            float accA = 0.f, accB = 0.f;
            const float* rA = Sh + fA * S_STRIDE;
            const float* rB = Sh + fB * S_STRIDE;   // may be OOB row; predicated below
            #pragma unroll
            for (int g4 = 0; g4 < 48; g4 += 4) {
                float4 aA = *(const float4*)(rA + g4);   // broadcast
                float4 aB = *(const float4*)(rB + g4);   // broadcast
                float v0 = Ps[(g4 + 0) * SP + 264 + jj]; // conflict-free rows of V
                float v1 = Ps[(g4 + 1) * SP + 264 + jj];
                float v2 = Ps[(g4 + 2) * SP + 264 + jj];
                float v3 = Ps[(g4 + 3) * SP + 264 + jj];
                accA = fmaf(aA.x, v0, fmaf(aA.y, v1, fmaf(aA.z, v2, fmaf(aA.w, v3, accA))));
                accB = fmaf(aB.x, v0, fmaf(aB.y, v1, fmaf(aB.z, v2, fmaf(aB.w, v3, accB))));
            }
            {   // tail g = 48, 49
                float v0 = Ps[48 * SP + 264 + jj];
                float v1 = Ps[49 * SP + 264 + jj];
                accA += rA[48] * v0 + rA[49] * v1;
                accB += rB[48] * v0 + rB[49] * v1;
            }
            float oA = accA + Ps[fA * SP + 396 + jj];
            outB[fA * CC + jj] = fmaxf(oA, 0.f);
            if (fB < FF) {
                float oB = accB + Ps[fB * SP + 396 + jj];
                outB[fB * CC + jj] = fmaxf(oB, 0.f);
            }
        }
    }
}

extern "C" void kernel_launch(void* const* d_in, const int* in_sizes, int n_in,
                              void* d_out, int out_size)
{
    const float* X  = (const float*)d_in[0];
    const float* Wq = (const float*)d_in[1];
    const float* Wk = (const float*)d_in[2];
    const float* Wv = (const float*)d_in[3];
    const float* Wr = (const float*)d_in[4];
    float* out = (float*)d_out;

    cudaFuncSetAttribute(autoint_kernel,
                         cudaFuncAttributeMaxDynamicSharedMemorySize, SMEM_BYTES);
    autoint_kernel<<<BB, 512, SMEM_BYTES>>>(X, Wq, Wk, Wv, Wr, out);
}